// round 1
// baseline (speedup 1.0000x reference)
#include <cuda_runtime.h>
#include <math.h>

#define N_NODES 100000
#define N_EDGES 3200000
#define IN_DIM  11
#define HID     32
#define SCAN_BLK 1024
#define N_SCAN_BLOCKS ((N_NODES + SCAN_BLK - 1) / SCAN_BLK)   // 98

// ---------------- scratch (static device globals; no allocation) ----------------
__device__ __align__(16) int   g_cnt[N_NODES];        // edge counts / cursor
__device__ __align__(16) int   g_rowptr[N_NODES + 1];
__device__ __align__(16) int   g_col[N_EDGES];
__device__ __align__(16) float g_dinv[N_NODES];
__device__ __align__(16) float g_y[N_NODES * HID];    // transformed+prescaled features
__device__ __align__(16) float g_h[N_NODES * HID];    // hidden activations
__device__ int g_blocksums[N_SCAN_BLOCKS];

// ---------------- kernels ----------------

__global__ void k_zero_cnt() {
    int i = blockIdx.x * blockDim.x + threadIdx.x;
    if (i < N_NODES) g_cnt[i] = 0;
}

__global__ void k_count(const int* __restrict__ dst) {
    int e = blockIdx.x * blockDim.x + threadIdx.x;
    if (e < N_EDGES) atomicAdd(&g_cnt[dst[e]], 1);
}

__global__ void k_dinv() {
    int v = blockIdx.x * blockDim.x + threadIdx.x;
    if (v < N_NODES) g_dinv[v] = rsqrtf((float)(g_cnt[v] + 1));  // +1 self-loop
}

// Block-local inclusive scan of g_cnt -> g_rowptr[i+1]; block totals out.
__global__ void k_scan1() {
    __shared__ int sh[SCAN_BLK];
    int t = threadIdx.x;
    int i = blockIdx.x * SCAN_BLK + t;
    int v = (i < N_NODES) ? g_cnt[i] : 0;
    sh[t] = v;
    __syncthreads();
    #pragma unroll
    for (int off = 1; off < SCAN_BLK; off <<= 1) {
        int add = (t >= off) ? sh[t - off] : 0;
        __syncthreads();
        sh[t] += add;
        __syncthreads();
    }
    if (i < N_NODES) g_rowptr[i + 1] = sh[t];
    if (t == SCAN_BLK - 1) g_blocksums[blockIdx.x] = sh[t];
}

__global__ void k_scan2() {
    if (threadIdx.x == 0 && blockIdx.x == 0) {
        int run = 0;
        for (int b = 0; b < N_SCAN_BLOCKS; b++) {
            int t = g_blocksums[b];
            g_blocksums[b] = run;
            run += t;
        }
    }
}

__global__ void k_scan3() {
    int t = threadIdx.x;
    int i = blockIdx.x * SCAN_BLK + t;
    if (i < N_NODES) g_rowptr[i + 1] += g_blocksums[blockIdx.x];
    if (i == 0) g_rowptr[0] = 0;
}

__global__ void k_fill(const int* __restrict__ src, const int* __restrict__ dst) {
    int e = blockIdx.x * blockDim.x + threadIdx.x;
    if (e < N_EDGES) {
        int d = dst[e];
        int pos = g_rowptr[d] + atomicAdd(&g_cnt[d], 1);
        g_col[pos] = src[e];
    }
}

// y[v][j] = dinv[v] * (x[v] @ W1)[j]
__global__ void k_xform1(const float* __restrict__ x, const float* __restrict__ W1) {
    __shared__ float Ws[IN_DIM * HID];
    for (int i = threadIdx.x; i < IN_DIM * HID; i += blockDim.x) Ws[i] = W1[i];
    __syncthreads();
    int gid = blockIdx.x * blockDim.x + threadIdx.x;
    if (gid >= N_NODES * HID) return;
    int v = gid >> 5, j = gid & 31;
    const float* xr = x + v * IN_DIM;
    float acc = 0.f;
    #pragma unroll
    for (int k = 0; k < IN_DIM; k++) acc += __ldg(&xr[k]) * Ws[k * HID + j];
    g_y[gid] = g_dinv[v] * acc;
}

// h[v] = relu(dinv[v] * (sum_{e:dst=v} y[src] + y[v]) + bias)
__global__ void k_agg(const float* __restrict__ bias) {
    int warp = (blockIdx.x * blockDim.x + threadIdx.x) >> 5;
    int lane = threadIdx.x & 31;
    if (warp >= N_NODES) return;
    int v = warp;
    float acc = g_y[v * HID + lane];          // self-loop term
    int s = g_rowptr[v], e = g_rowptr[v + 1];
    for (int i = s; i < e; i += 32) {
        int idx = (i + lane < e) ? __ldg(&g_col[i + lane]) : 0;
        int m = min(32, e - i);
        for (int k = 0; k < m; k++) {
            int sidx = __shfl_sync(0xffffffffu, idx, k);
            acc += __ldg(&g_y[sidx * HID + lane]);
        }
    }
    float r = g_dinv[v] * acc + __ldg(&bias[lane]);
    g_h[v * HID + lane] = fmaxf(r, 0.f);
}

// y[v][j] = dinv[v] * (h[v] @ W2)[j]   (warp per node, shuffle-broadcast)
__global__ void k_xform2(const float* __restrict__ W2) {
    __shared__ float Ws[HID * HID];
    for (int i = threadIdx.x; i < HID * HID; i += blockDim.x) Ws[i] = W2[i];
    __syncthreads();
    int warp = (blockIdx.x * blockDim.x + threadIdx.x) >> 5;
    int lane = threadIdx.x & 31;
    if (warp >= N_NODES) return;
    float hval = g_h[warp * HID + lane];
    float acc = 0.f;
    #pragma unroll
    for (int k = 0; k < HID; k++) {
        float b = __shfl_sync(0xffffffffu, hval, k);
        acc += b * Ws[k * HID + lane];
    }
    g_y[warp * HID + lane] = g_dinv[warp] * acc;
}

// out[v] = elu(h[v] @ Wo1 + bo1) @ Wo2 + bo2
__global__ void k_mlp(const float* __restrict__ Wo1, const float* __restrict__ bo1,
                      const float* __restrict__ Wo2, const float* __restrict__ bo2,
                      float* __restrict__ out) {
    __shared__ float W1s[HID * 16];
    __shared__ float b1s[16];
    __shared__ float W2s[16];
    __shared__ float b2s;
    for (int i = threadIdx.x; i < HID * 16; i += blockDim.x) W1s[i] = Wo1[i];
    if (threadIdx.x < 16) { b1s[threadIdx.x] = bo1[threadIdx.x]; W2s[threadIdx.x] = Wo2[threadIdx.x]; }
    if (threadIdx.x == 0) b2s = bo2[0];
    __syncthreads();
    int v = blockIdx.x * blockDim.x + threadIdx.x;
    if (v >= N_NODES) return;
    float h[HID];
    const float4* hp = (const float4*)(g_h + v * HID);
    #pragma unroll
    for (int q = 0; q < HID / 4; q++) {
        float4 f = hp[q];
        h[q * 4 + 0] = f.x; h[q * 4 + 1] = f.y; h[q * 4 + 2] = f.z; h[q * 4 + 3] = f.w;
    }
    float o = b2s;
    #pragma unroll
    for (int j = 0; j < 16; j++) {
        float a = b1s[j];
        #pragma unroll
        for (int k = 0; k < HID; k++) a += h[k] * W1s[k * 16 + j];
        float e = (a > 0.f) ? a : expm1f(a);   // ELU, alpha=1
        o += e * W2s[j];
    }
    out[v] = o;
}

// ---------------- launch ----------------
extern "C" void kernel_launch(void* const* d_in, const int* in_sizes, int n_in,
                              void* d_out, int out_size) {
    const float* x   = (const float*)d_in[0];
    const int*   ei  = (const int*)d_in[1];
    // d_in[2] = batch (unused; single graph, output is per-node)
    const float* W1  = (const float*)d_in[3];
    const float* b1  = (const float*)d_in[4];
    const float* W2  = (const float*)d_in[5];
    const float* b2  = (const float*)d_in[6];
    const float* Wo1 = (const float*)d_in[7];
    const float* bo1 = (const float*)d_in[8];
    const float* Wo2 = (const float*)d_in[9];
    const float* bo2 = (const float*)d_in[10];
    float* out = (float*)d_out;

    const int* src = ei;              // row 0
    const int* dst = ei + N_EDGES;    // row 1

    const int TB = 256;
    int nodeBlocks = (N_NODES + TB - 1) / TB;
    int edgeBlocks = (N_EDGES + TB - 1) / TB;
    int warpNodeBlocks = (N_NODES * 32 + TB - 1) / TB;   // warp-per-node kernels

    // degree / normalization
    k_zero_cnt<<<nodeBlocks, TB>>>();
    k_count<<<edgeBlocks, TB>>>(dst);
    k_dinv<<<nodeBlocks, TB>>>();

    // CSR build (by destination)
    k_scan1<<<N_SCAN_BLOCKS, SCAN_BLK>>>();
    k_scan2<<<1, 32>>>();
    k_scan3<<<N_SCAN_BLOCKS, SCAN_BLK>>>();
    k_zero_cnt<<<nodeBlocks, TB>>>();
    k_fill<<<edgeBlocks, TB>>>(src, dst);

    // GCN layer 1
    k_xform1<<<warpNodeBlocks, TB>>>(x, W1);
    k_agg<<<warpNodeBlocks, TB>>>(b1);

    // GCN layer 2
    k_xform2<<<warpNodeBlocks, TB>>>(W2);
    k_agg<<<warpNodeBlocks, TB>>>(b2);

    // output MLP
    k_mlp<<<nodeBlocks, TB>>>(Wo1, bo1, Wo2, bo2, out);
}

// round 2
// speedup vs baseline: 1.0847x; 1.0847x over previous
#include <cuda_runtime.h>
#include <cuda_fp16.h>
#include <math.h>

#define N_NODES 100000
#define N_EDGES 3200000
#define IN_DIM  11
#define HID     32
#define SCAN_BLK 1024
#define N_SCAN_BLOCKS ((N_NODES + SCAN_BLK - 1) / SCAN_BLK)   // 98

// ---------------- scratch (static device globals; no allocation) ----------------
__device__ __align__(16) int    g_cnt[N_NODES];        // edge counts / cursor
__device__ __align__(16) int    g_rowptr[N_NODES + 1];
__device__ __align__(16) int    g_col[N_EDGES];
__device__ __align__(16) float  g_dinv[N_NODES];
__device__ __align__(16) __half g_y1[N_NODES * HID];   // layer-1 prescaled features (fp16)
__device__ __align__(16) __half g_y2[N_NODES * HID];   // layer-2 prescaled features (fp16)
__device__ int g_blocksums[N_SCAN_BLOCKS];

// ---------------- CSR build ----------------

__global__ void k_zero_cnt() {
    int i = blockIdx.x * blockDim.x + threadIdx.x;
    if (i < N_NODES) g_cnt[i] = 0;
}

__global__ void k_count(const int* __restrict__ dst) {
    int e4 = blockIdx.x * blockDim.x + threadIdx.x;
    if (e4 * 4 + 3 < N_EDGES) {
        int4 d = ((const int4*)dst)[e4];
        atomicAdd(&g_cnt[d.x], 1);
        atomicAdd(&g_cnt[d.y], 1);
        atomicAdd(&g_cnt[d.z], 1);
        atomicAdd(&g_cnt[d.w], 1);
    } else {
        for (int e = e4 * 4; e < N_EDGES; e++) atomicAdd(&g_cnt[dst[e]], 1);
    }
}

// inclusive block scan of cnt -> rowptr[i+1]; block totals out; also dinv
__global__ void k_scan1() {
    __shared__ int sh[SCAN_BLK];
    int t = threadIdx.x;
    int i = blockIdx.x * SCAN_BLK + t;
    int v = (i < N_NODES) ? g_cnt[i] : 0;
    if (i < N_NODES) g_dinv[i] = rsqrtf((float)(v + 1));  // +1 self-loop
    sh[t] = v;
    __syncthreads();
    #pragma unroll
    for (int off = 1; off < SCAN_BLK; off <<= 1) {
        int add = (t >= off) ? sh[t - off] : 0;
        __syncthreads();
        sh[t] += add;
        __syncthreads();
    }
    if (i < N_NODES) g_rowptr[i + 1] = sh[t];
    if (t == SCAN_BLK - 1) g_blocksums[blockIdx.x] = sh[t];
}

__global__ void k_scan2() {
    if (threadIdx.x == 0) {
        int run = 0;
        for (int b = 0; b < N_SCAN_BLOCKS; b++) {
            int t = g_blocksums[b];
            g_blocksums[b] = run;
            run += t;
        }
    }
}

__global__ void k_scan3() {
    int t = threadIdx.x;
    int i = blockIdx.x * SCAN_BLK + t;
    if (i < N_NODES) {
        g_rowptr[i + 1] += g_blocksums[blockIdx.x];
        g_cnt[i] = 0;                       // reset cursor for fill
    }
    if (i == 0) g_rowptr[0] = 0;
}

__global__ void k_fill(const int* __restrict__ src, const int* __restrict__ dst) {
    int e4 = blockIdx.x * blockDim.x + threadIdx.x;
    if (e4 * 4 + 3 < N_EDGES) {
        int4 s = ((const int4*)src)[e4];
        int4 d = ((const int4*)dst)[e4];
        g_col[g_rowptr[d.x] + atomicAdd(&g_cnt[d.x], 1)] = s.x;
        g_col[g_rowptr[d.y] + atomicAdd(&g_cnt[d.y], 1)] = s.y;
        g_col[g_rowptr[d.z] + atomicAdd(&g_cnt[d.z], 1)] = s.z;
        g_col[g_rowptr[d.w] + atomicAdd(&g_cnt[d.w], 1)] = s.w;
    } else {
        for (int e = e4 * 4; e < N_EDGES; e++) {
            int d = dst[e];
            g_col[g_rowptr[d] + atomicAdd(&g_cnt[d], 1)] = src[e];
        }
    }
}

// ---------------- layer 1 transform:  y1[v][j] = dinv[v] * (x[v] @ W1)[j] ----------------
__global__ void k_xform1(const float* __restrict__ x, const float* __restrict__ W1) {
    __shared__ float Ws[IN_DIM * HID];
    for (int i = threadIdx.x; i < IN_DIM * HID; i += blockDim.x) Ws[i] = W1[i];
    __syncthreads();
    int gid = blockIdx.x * blockDim.x + threadIdx.x;
    if (gid >= N_NODES * HID) return;
    int v = gid >> 5, j = gid & 31;
    const float* xr = x + v * IN_DIM;
    float acc = 0.f;
    #pragma unroll
    for (int k = 0; k < IN_DIM; k++) acc += __ldg(&xr[k]) * Ws[k * HID + j];
    g_y1[gid] = __float2half_rn(g_dinv[v] * acc);
}

// ---------------- agg layer 1 fused with xform2 ----------------
// h1 = relu(dinv*(sum y1[src] + y1[v]) + b1);  y2 = dinv * (h1 @ W2)  (fp16)
__global__ void k_agg1(const float* __restrict__ b1, const float* __restrict__ W2) {
    __shared__ float W2s[HID * HID];
    __shared__ float b1s[HID];
    for (int i = threadIdx.x; i < HID * HID; i += blockDim.x) W2s[i] = W2[i];
    if (threadIdx.x < HID) b1s[threadIdx.x] = b1[threadIdx.x];
    __syncthreads();

    int warp = (blockIdx.x * blockDim.x + threadIdx.x) >> 5;
    int lane = threadIdx.x & 31;
    if (warp >= N_NODES) return;
    int v = warp;
    float dinv = g_dinv[v];
    float acc = __half2float(g_y1[v * HID + lane]);   // self-loop
    int s = g_rowptr[v], e = g_rowptr[v + 1];
    for (int i = s; i < e; i += 32) {
        int idx = (i + lane < e) ? __ldg(&g_col[i + lane]) : 0;
        int m = min(32, e - i);
        for (int k = 0; k < m; k++) {
            int sidx = __shfl_sync(0xffffffffu, idx, k);
            acc += __half2float(g_y1[sidx * HID + lane]);
        }
    }
    float h = fmaxf(dinv * acc + b1s[lane], 0.f);

    // fused xform2 via shuffle broadcast
    float yacc = 0.f;
    #pragma unroll
    for (int k = 0; k < HID; k++) {
        float hk = __shfl_sync(0xffffffffu, h, k);
        yacc += hk * W2s[k * HID + lane];
    }
    g_y2[v * HID + lane] = __float2half_rn(dinv * yacc);
}

// ---------------- agg layer 2 fused with output MLP ----------------
// h2 = relu(dinv*(sum y2[src] + y2[v]) + b2);  out = elu(h2@Wo1+bo1)@Wo2 + bo2
__global__ void k_agg2(const float* __restrict__ b2,
                       const float* __restrict__ Wo1, const float* __restrict__ bo1,
                       const float* __restrict__ Wo2, const float* __restrict__ bo2,
                       float* __restrict__ out) {
    __shared__ float Wo1s[HID * 16];
    __shared__ float b2s[HID];
    __shared__ float bo1s[16];
    __shared__ float Wo2s[16];
    __shared__ float bo2s;
    for (int i = threadIdx.x; i < HID * 16; i += blockDim.x) Wo1s[i] = Wo1[i];
    if (threadIdx.x < HID) b2s[threadIdx.x] = b2[threadIdx.x];
    if (threadIdx.x < 16) { bo1s[threadIdx.x] = bo1[threadIdx.x]; Wo2s[threadIdx.x] = Wo2[threadIdx.x]; }
    if (threadIdx.x == 0) bo2s = bo2[0];
    __syncthreads();

    int warp = (blockIdx.x * blockDim.x + threadIdx.x) >> 5;
    int lane = threadIdx.x & 31;
    if (warp >= N_NODES) return;
    int v = warp;
    float dinv = g_dinv[v];
    float acc = __half2float(g_y2[v * HID + lane]);   // self-loop
    int s = g_rowptr[v], e = g_rowptr[v + 1];
    for (int i = s; i < e; i += 32) {
        int idx = (i + lane < e) ? __ldg(&g_col[i + lane]) : 0;
        int m = min(32, e - i);
        for (int k = 0; k < m; k++) {
            int sidx = __shfl_sync(0xffffffffu, idx, k);
            acc += __half2float(g_y2[sidx * HID + lane]);
        }
    }
    float h = fmaxf(dinv * acc + b2s[lane], 0.f);

    // fused MLP: a_j (j<16) via shuffle broadcast of h over k
    float a = (lane < 16) ? bo1s[lane] : 0.f;
    #pragma unroll
    for (int k = 0; k < HID; k++) {
        float hk = __shfl_sync(0xffffffffu, h, k);
        if (lane < 16) a += hk * Wo1s[k * 16 + lane];
    }
    float ev = 0.f;
    if (lane < 16) {
        float el = (a > 0.f) ? a : expm1f(a);   // ELU alpha=1
        ev = el * Wo2s[lane];
    }
    // reduce 16 partials (lanes >=16 hold 0)
    #pragma unroll
    for (int off = 16; off >= 1; off >>= 1)
        ev += __shfl_xor_sync(0xffffffffu, ev, off);
    if (lane == 0) out[v] = ev + bo2s;
}

// ---------------- launch ----------------
extern "C" void kernel_launch(void* const* d_in, const int* in_sizes, int n_in,
                              void* d_out, int out_size) {
    const float* x   = (const float*)d_in[0];
    const int*   ei  = (const int*)d_in[1];
    const float* W1  = (const float*)d_in[3];
    const float* b1  = (const float*)d_in[4];
    const float* W2  = (const float*)d_in[5];
    const float* b2  = (const float*)d_in[6];
    const float* Wo1 = (const float*)d_in[7];
    const float* bo1 = (const float*)d_in[8];
    const float* Wo2 = (const float*)d_in[9];
    const float* bo2 = (const float*)d_in[10];
    float* out = (float*)d_out;

    const int* src = ei;              // row 0
    const int* dst = ei + N_EDGES;    // row 1

    const int TB = 256;
    int nodeBlocks = (N_NODES + TB - 1) / TB;
    int edge4Blocks = ((N_EDGES + 3) / 4 + TB - 1) / TB;
    int warpNodeBlocks = (N_NODES * 32 + TB - 1) / TB;

    // CSR build (by destination) + dinv
    k_zero_cnt<<<nodeBlocks, TB>>>();
    k_count<<<edge4Blocks, TB>>>(dst);
    k_scan1<<<N_SCAN_BLOCKS, SCAN_BLK>>>();
    k_scan2<<<1, 32>>>();
    k_scan3<<<N_SCAN_BLOCKS, SCAN_BLK>>>();
    k_fill<<<edge4Blocks, TB>>>(src, dst);

    // GCN layer 1 (+xform2 fused)
    k_xform1<<<warpNodeBlocks, TB>>>(x, W1);
    k_agg1<<<warpNodeBlocks, TB>>>(b1, W2);

    // GCN layer 2 (+output MLP fused)
    k_agg2<<<warpNodeBlocks, TB>>>(b2, Wo1, bo1, Wo2, bo2, out);
}